// round 17
// baseline (speedup 1.0000x reference)
#include <cuda_runtime.h>
#include <cuda_bf16.h>
#include <cstdint>
#include <math.h>

#define BB 4
#define TT 2048
#define CC 1024
#define HH 16
#define DD 64
#define MM (BB*TT)          // 8192
#define NQKV (3*CC)         // 3072

// ---------------- scratch (device globals; no allocs allowed) --------------
__device__ __nv_bfloat16 g_qhi[(size_t)BB*HH*TT*DD], g_qlo[(size_t)BB*HH*TT*DD];
__device__ __nv_bfloat16 g_khi[(size_t)BB*HH*TT*DD], g_klo[(size_t)BB*HH*TT*DD];
__device__ __nv_bfloat16 g_vhi[(size_t)BB*HH*TT*DD], g_vlo[(size_t)BB*HH*TT*DD];
__device__ __nv_bfloat16 g_xhi[(size_t)MM*CC],  g_xlo[(size_t)MM*CC];
__device__ __nv_bfloat16 g_wahi[(size_t)NQKV*CC], g_walo[(size_t)NQKV*CC]; // [N][K] K-major
__device__ __nv_bfloat16 g_wphi[(size_t)CC*CC],   g_wplo[(size_t)CC*CC];   // [N][K]
__device__ __nv_bfloat16 g_yhi[(size_t)MM*CC],  g_ylo[(size_t)MM*CC];

__device__ __forceinline__ uint32_t smem_u32(const void* p) {
    uint32_t a;
    asm("{ .reg .u64 t; cvta.to.shared.u64 t, %1; cvt.u32.u64 %0, t; }" : "=r"(a) : "l"(p));
    return a;
}
__device__ __forceinline__ uint64_t gmem_u64(const void* p) {
    uint64_t a;
    asm("cvta.to.global.u64 %0, %1;" : "=l"(a) : "l"(p));
    return a;
}

// ldmatrix x4 (non-trans / trans) -- base PTX
#define LDSM4(r0, r1, r2, r3, addr) \
    asm volatile("ldmatrix.sync.aligned.m8n8.x4.shared.b16 {%0,%1,%2,%3}, [%4];" \
        : "=r"(r0), "=r"(r1), "=r"(r2), "=r"(r3) : "r"(addr))
#define LDSM4T(r0, r1, r2, r3, addr) \
    asm volatile("ldmatrix.sync.aligned.m8n8.x4.trans.shared.b16 {%0,%1,%2,%3}, [%4];" \
        : "=r"(r0), "=r"(r1), "=r"(r2), "=r"(r3) : "r"(addr))

// mma m16n8k16 bf16 -> f32 -- base PTX, sm_80+
#define MMA16816(d, a0, a1, a2, a3, b0, b1) \
    asm volatile("mma.sync.aligned.m16n8k16.row.col.f32.bf16.bf16.f32 " \
        "{%0,%1,%2,%3}, {%4,%5,%6,%7}, {%8,%9}, {%0,%1,%2,%3};" \
        : "+f"((d)[0]), "+f"((d)[1]), "+f"((d)[2]), "+f"((d)[3]) \
        : "r"(a0), "r"(a1), "r"(a2), "r"(a3), "r"(b0), "r"(b1))

// cp.async 16B -- base PTX, sm_80+
#define CPA16(saddr, gaddr) \
    asm volatile("cp.async.cg.shared.global [%0], [%1], 16;" :: "r"(saddr), "l"(gaddr))
#define CPA_COMMIT() asm volatile("cp.async.commit_group;" ::: "memory")
#define CPA_WAIT1()  asm volatile("cp.async.wait_group 1;" ::: "memory")

// split two fp32 into packed bf16x2 hi + bf16x2 lo (elem0 -> low half)
__device__ __forceinline__ void split2(float a, float b, uint32_t& hi, uint32_t& lo) {
    __nv_bfloat16 ha = __float2bfloat16(a), hb = __float2bfloat16(b);
    __nv_bfloat162 H; H.x = ha; H.y = hb;
    __nv_bfloat162 L;
    L.x = __float2bfloat16(a - __bfloat162float(ha));
    L.y = __float2bfloat16(b - __bfloat162float(hb));
    hi = *(uint32_t*)&H; lo = *(uint32_t*)&L;
}

// ---------------- prep kernels ---------------------------------------------
__global__ __launch_bounds__(256)
void split_x_kernel(const float* __restrict__ x)
{
    const int idx = blockIdx.x * 256 + threadIdx.x;
    if ((size_t)idx * 4 >= (size_t)MM * CC) return;
    const float4 v = ((const float4*)x)[idx];
    __nv_bfloat162 h01, h23, l01, l23;
    h01.x = __float2bfloat16(v.x); h01.y = __float2bfloat16(v.y);
    h23.x = __float2bfloat16(v.z); h23.y = __float2bfloat16(v.w);
    l01.x = __float2bfloat16(v.x - __bfloat162float(h01.x));
    l01.y = __float2bfloat16(v.y - __bfloat162float(h01.y));
    l23.x = __float2bfloat16(v.z - __bfloat162float(h23.x));
    l23.y = __float2bfloat16(v.w - __bfloat162float(h23.y));
    ((__nv_bfloat162*)g_xhi)[idx * 2]     = h01;
    ((__nv_bfloat162*)g_xhi)[idx * 2 + 1] = h23;
    ((__nv_bfloat162*)g_xlo)[idx * 2]     = l01;
    ((__nv_bfloat162*)g_xlo)[idx * 2 + 1] = l23;
}

__global__ __launch_bounds__(256)
void transpose_split_kernel(const float* __restrict__ W,
                            __nv_bfloat16* __restrict__ Thi,
                            __nv_bfloat16* __restrict__ Tlo, int N)
{
    __shared__ float tile[32][33];
    const int tx = threadIdx.x, ty = threadIdx.y;            // 32 x 8
    const int nbase = blockIdx.x * 32, kbase = blockIdx.y * 32;
#pragma unroll
    for (int i = 0; i < 4; i++)
        tile[ty + i * 8][tx] = W[(size_t)(kbase + ty + i * 8) * N + nbase + tx];
    __syncthreads();
#pragma unroll
    for (int i = 0; i < 4; i++) {
        const int n = nbase + ty + i * 8;
        const int k = kbase + tx;
        const float v = tile[tx][ty + i * 8];
        const __nv_bfloat16 h = __float2bfloat16(v);
        Thi[(size_t)n * CC + k] = h;
        Tlo[(size_t)n * CC + k] = __float2bfloat16(v - __bfloat162float(h));
    }
}

// ---------------- cp.async 3-stage mma.sync bf16x3 GEMM --------------------
// K chunks of 32 halves; 3 smem stages of 384 rows x 40 halves (30720 B each).
// Row stride 80 B: 16B-aligned for cp.async, conflict-free for ldmatrix
// (8-row phase hits banks 20*i mod 32 = all distinct).
// EPI==0: bias (+q scale 1/8) + split + scatter to g_{q,k,v}{hi,lo}.
// EPI==1: out + bias (fp32).
#define GROW 40
#define GSTG (384 * GROW * 2)     // bytes per stage
#define NCHUNK 32                 // CC / 32
template<int EPI>
__global__ __launch_bounds__(256)
void gemm_mma_bf16x3(const __nv_bfloat16* __restrict__ Ahi, const __nv_bfloat16* __restrict__ Alo,
                     const __nv_bfloat16* __restrict__ Bhi, const __nv_bfloat16* __restrict__ Blo,
                     const float* __restrict__ bias, float* __restrict__ out)
{
    extern __shared__ __nv_bfloat16 smem[];   // 3 stages
    const uint32_t sb = smem_u32(smem);
    const int tid = threadIdx.x;
    const int lane = tid & 31, w = tid >> 5;
    const int wm = w & 3, wn = w >> 2;
    const int bn = blockIdx.x, bm = blockIdx.y;

    // per-thread cp.async source/dest (6 x 16B per chunk)
    uint64_t gsrc[6];
    uint32_t sdst[6];
#pragma unroll
    for (int i = 0; i < 6; ++i) {
        const int idx = tid + 256 * i;            // 0..1535
        const int r = idx >> 2, cg = idx & 3;     // row, 16B-group (4 per row)
        const __nv_bfloat16* src;
        int grow;
        if (r < 128)      { src = Ahi; grow = bm * 128 + r; }
        else if (r < 256) { src = Alo; grow = bm * 128 + (r - 128); }
        else if (r < 320) { src = Bhi; grow = bn * 64 + (r - 256); }
        else              { src = Blo; grow = bn * 64 + (r - 320); }
        gsrc[i] = gmem_u64(src + (size_t)grow * CC + cg * 8);
        sdst[i] = sb + 2u * (r * GROW + cg * 8);  // r*80 + cg*16 bytes: 16B-aligned
    }

    // fragment smem offsets (stage-relative, bytes)
    const int q4   = lane >> 3;
    const int rowA = (lane & 7) + (q4 & 1) * 8;
    const int kA   = (q4 >> 1) * 8;
    const int rowB = (lane & 7) + ((lane >> 4) & 1) * 8;
    const int kB   = ((lane >> 3) & 1) * 8;

    uint32_t offAH[2], offAL[2], offBH[2], offBL[2];
#pragma unroll
    for (int mt = 0; mt < 2; ++mt) {
        offAH[mt] = 2u * ((wm * 32 + mt * 16 + rowA) * GROW + kA);
        offAL[mt] = offAH[mt] + 2u * 128 * GROW;
    }
#pragma unroll
    for (int p = 0; p < 2; ++p) {
        offBH[p] = 2u * ((256 + wn * 32 + p * 16 + rowB) * GROW + kB);
        offBL[p] = offBH[p] + 2u * 64 * GROW;
    }

    float acc[2][4][4];
#pragma unroll
    for (int mt = 0; mt < 2; ++mt)
#pragma unroll
        for (int nt = 0; nt < 4; ++nt)
#pragma unroll
            for (int e = 0; e < 4; ++e) acc[mt][nt][e] = 0.f;

    // prologue: stage chunks 0 and 1
#pragma unroll
    for (int c = 0; c < 2; ++c) {
#pragma unroll
        for (int i = 0; i < 6; ++i)
            CPA16(sdst[i] + c * GSTG, gsrc[i] + c * 64u);   // 32 halves = 64 B
        CPA_COMMIT();
    }

#pragma unroll 1
    for (int ck = 0; ck < NCHUNK; ++ck) {
        CPA_WAIT1();
        __syncthreads();

        // issue loads for chunk ck+2 into stage (ck+2)%3
        if (ck + 2 < NCHUNK) {
            const uint32_t stoff = (uint32_t)((ck + 2) % 3) * GSTG;
            const uint64_t goff = (uint64_t)(ck + 2) * 64u;
#pragma unroll
            for (int i = 0; i < 6; ++i)
                CPA16(sdst[i] + stoff, gsrc[i] + goff);
        }
        CPA_COMMIT();

        // compute chunk ck from stage ck%3 (2 k16 steps)
        const uint32_t sbs = sb + (uint32_t)(ck % 3) * GSTG;
#pragma unroll
        for (int ks = 0; ks < 2; ++ks) {
            const uint32_t koff = ks * 32;   // 16 halves
            uint32_t ah[2][4], al[2][4], bh[2][4], bl[2][4];
#pragma unroll
            for (int mt = 0; mt < 2; ++mt) {
                LDSM4(ah[mt][0], ah[mt][1], ah[mt][2], ah[mt][3], sbs + offAH[mt] + koff);
                LDSM4(al[mt][0], al[mt][1], al[mt][2], al[mt][3], sbs + offAL[mt] + koff);
            }
#pragma unroll
            for (int p = 0; p < 2; ++p) {
                LDSM4(bh[p][0], bh[p][1], bh[p][2], bh[p][3], sbs + offBH[p] + koff);
                LDSM4(bl[p][0], bl[p][1], bl[p][2], bl[p][3], sbs + offBL[p] + koff);
            }
#pragma unroll
            for (int mt = 0; mt < 2; ++mt)
#pragma unroll
                for (int p = 0; p < 2; ++p)
#pragma unroll
                    for (int t = 0; t < 2; ++t) {
                        const int nt = p * 2 + t;
                        MMA16816(acc[mt][nt], ah[mt][0], ah[mt][1], ah[mt][2], ah[mt][3],
                                 bh[p][t * 2], bh[p][t * 2 + 1]);
                        MMA16816(acc[mt][nt], ah[mt][0], ah[mt][1], ah[mt][2], ah[mt][3],
                                 bl[p][t * 2], bl[p][t * 2 + 1]);
                        MMA16816(acc[mt][nt], al[mt][0], al[mt][1], al[mt][2], al[mt][3],
                                 bh[p][t * 2], bh[p][t * 2 + 1]);
                    }
        }
        __syncthreads();
    }

    const int g = lane >> 2, tg = lane & 3;
#pragma unroll
    for (int mt = 0; mt < 2; ++mt)
#pragma unroll
        for (int nt = 0; nt < 4; ++nt) {
            const int col = bn * 64 + wn * 32 + nt * 8 + tg * 2;
            const float bi0 = bias[col], bi1 = bias[col + 1];
#pragma unroll
            for (int half = 0; half < 2; ++half) {
                const int row = bm * 128 + wm * 32 + mt * 16 + g + half * 8;
                float v0 = acc[mt][nt][half * 2]     + bi0;
                float v1 = acc[mt][nt][half * 2 + 1] + bi1;
                if (EPI == 0) {
                    const int b = row >> 11, tt = row & (TT - 1);
                    const int sel = col >> 10;
                    const int c = col & (CC - 1);
                    const int h = c >> 6, d = c & 63;
                    if (sel == 0) { v0 *= 0.125f; v1 *= 0.125f; }   // fold 1/sqrt(D)
                    __nv_bfloat16* dh = (sel == 0) ? g_qhi : (sel == 1) ? g_khi : g_vhi;
                    __nv_bfloat16* dl = (sel == 0) ? g_qlo : (sel == 1) ? g_klo : g_vlo;
                    uint32_t hi, lo;
                    split2(v0, v1, hi, lo);
                    const size_t o2 = ((size_t)(b * HH + h) * TT + tt) * DD + d;
                    *(uint32_t*)(dh + o2) = hi;
                    *(uint32_t*)(dl + o2) = lo;
                } else {
                    float2* p2 = (float2*)&out[(size_t)row * CC + col];
                    *p2 = make_float2(v0, v1);
                }
            }
        }
}

// ---------------- FA2-style mma.sync attention (bf16x3, validated R13) -----
#define SROW 72
__global__ __launch_bounds__(256)
void attn_mma_kernel()
{
    __shared__ __nv_bfloat16 sm[256 * SROW];
    const uint32_t sb = smem_u32(sm);
    const int tid = threadIdx.x, lane = tid & 31, w = tid >> 5;
    const int qt = blockIdx.x, h = blockIdx.y, b = blockIdx.z;
    const int qrow0 = qt * 128;
    const size_t base = (size_t)(b * HH + h) * TT * DD;

    const int q4   = lane >> 3;
    const int rowA = (lane & 7) + (q4 & 1) * 8;
    const int kA   = (q4 >> 1) * 8;
    const int rowB = (lane & 7) + ((lane >> 4) & 1) * 8;
    const int kB   = ((lane >> 3) & 1) * 8;
    const int g = lane >> 2, tg = lane & 3;

#pragma unroll
    for (int i = 0; i < 8; ++i) {
        const int idx = tid + 256 * i;
        const int r = (idx >> 3) & 127, cg = idx & 7;
        const __nv_bfloat16* src = (idx < 1024) ? g_qhi : g_qlo;
        const int srow = ((idx < 1024) ? 0 : 128) + r;
        const uint4 v = *(const uint4*)(src + base + (size_t)(qrow0 + r) * DD + cg * 8);
        *(uint4*)((char*)sm + ((size_t)srow * SROW + cg * 8) * 2) = v;
    }
    __syncthreads();

    uint32_t qh[4][4], ql[4][4];
#pragma unroll
    for (int ks = 0; ks < 4; ++ks) {
        const uint32_t a = sb + 2u * ((w * 16 + rowA) * SROW + ks * 16 + kA);
        LDSM4(qh[ks][0], qh[ks][1], qh[ks][2], qh[ks][3], a);
        LDSM4(ql[ks][0], ql[ks][1], ql[ks][2], ql[ks][3], a + 2u * 128 * SROW);
    }
    __syncthreads();

    float o[8][4];
#pragma unroll
    for (int dt = 0; dt < 8; ++dt)
#pragma unroll
        for (int e = 0; e < 4; ++e) o[dt][e] = 0.f;
    float mrow[2] = {-1e30f, -1e30f}, lrow[2] = {0.f, 0.f};

    const int wr0 = qrow0 + w * 16;
    const int nkv = 2 * (qt + 1);

#pragma unroll 1
    for (int kt = 0; kt < nkv; ++kt) {
        const int kvbase = kt * 64;
#pragma unroll
        for (int i = 0; i < 8; ++i) {
            const int idx = tid + 256 * i;
            const int a = idx >> 9;
            const int r = (idx >> 3) & 63, cg = idx & 7;
            const __nv_bfloat16* src = (a == 0) ? g_khi : (a == 1) ? g_klo
                                     : (a == 2) ? g_vhi : g_vlo;
            const uint4 v = *(const uint4*)(src + base + (size_t)(kvbase + r) * DD + cg * 8);
            *(uint4*)((char*)sm + ((size_t)(a * 64 + r) * SROW + cg * 8) * 2) = v;
        }
        __syncthreads();

        float s[8][4];
#pragma unroll
        for (int nt = 0; nt < 8; ++nt)
#pragma unroll
            for (int e = 0; e < 4; ++e) s[nt][e] = 0.f;

#pragma unroll
        for (int ks = 0; ks < 4; ++ks)
#pragma unroll
            for (int p = 0; p < 4; ++p) {
                const uint32_t ka = sb + 2u * ((p * 16 + rowB) * SROW + ks * 16 + kB);
                uint32_t kh0, kh1, kh2, kh3, kl0, kl1, kl2, kl3;
                LDSM4(kh0, kh1, kh2, kh3, ka);
                LDSM4(kl0, kl1, kl2, kl3, ka + 2u * 64 * SROW);
                MMA16816(s[2*p],   qh[ks][0], qh[ks][1], qh[ks][2], qh[ks][3], kh0, kh1);
                MMA16816(s[2*p],   qh[ks][0], qh[ks][1], qh[ks][2], qh[ks][3], kl0, kl1);
                MMA16816(s[2*p],   ql[ks][0], ql[ks][1], ql[ks][2], ql[ks][3], kh0, kh1);
                MMA16816(s[2*p+1], qh[ks][0], qh[ks][1], qh[ks][2], qh[ks][3], kh2, kh3);
                MMA16816(s[2*p+1], qh[ks][0], qh[ks][1], qh[ks][2], qh[ks][3], kl2, kl3);
                MMA16816(s[2*p+1], ql[ks][0], ql[ks][1], ql[ks][2], ql[ks][3], kh2, kh3);
            }

        if (kvbase + 63 > wr0) {
#pragma unroll
            for (int nt = 0; nt < 8; ++nt)
#pragma unroll
                for (int e = 0; e < 4; ++e) {
                    const int col = kvbase + nt * 8 + tg * 2 + (e & 1);
                    const int row = wr0 + g + (e >> 1) * 8;
                    if (col > row) s[nt][e] = -1e30f;
                }
        }

#pragma unroll
        for (int i = 0; i < 2; ++i) {
            float rm = -1e30f;
#pragma unroll
            for (int nt = 0; nt < 8; ++nt)
                rm = fmaxf(rm, fmaxf(s[nt][i*2], s[nt][i*2+1]));
            rm = fmaxf(rm, __shfl_xor_sync(0xffffffffu, rm, 1));
            rm = fmaxf(rm, __shfl_xor_sync(0xffffffffu, rm, 2));
            const float mn = fmaxf(mrow[i], rm);
            const float corr = __expf(mrow[i] - mn);
            mrow[i] = mn;
            float rs = 0.f;
#pragma unroll
            for (int nt = 0; nt < 8; ++nt) {
                const float p0 = __expf(s[nt][i*2] - mn);
                const float p1 = __expf(s[nt][i*2+1] - mn);
                s[nt][i*2] = p0; s[nt][i*2+1] = p1;
                rs += p0 + p1;
            }
            rs += __shfl_xor_sync(0xffffffffu, rs, 1);
            rs += __shfl_xor_sync(0xffffffffu, rs, 2);
            lrow[i] = lrow[i] * corr + rs;
#pragma unroll
            for (int dt = 0; dt < 8; ++dt) {
                o[dt][i*2]   *= corr;
                o[dt][i*2+1] *= corr;
            }
        }

#pragma unroll
        for (int p = 0; p < 4; ++p) {
            uint32_t ph[4], pl[4];
            split2(s[2*p][0],   s[2*p][1],   ph[0], pl[0]);
            split2(s[2*p][2],   s[2*p][3],   ph[1], pl[1]);
            split2(s[2*p+1][0], s[2*p+1][1], ph[2], pl[2]);
            split2(s[2*p+1][2], s[2*p+1][3], ph[3], pl[3]);

            const int vrow = (lane & 7) + ((lane >> 3) & 1) * 8;
            const int vcolb = (lane >> 4) * 8;
#pragma unroll
            for (int dt2 = 0; dt2 < 4; ++dt2) {
                const uint32_t va = sb + 2u * ((128 + p * 16 + vrow) * SROW + dt2 * 16 + vcolb);
                uint32_t vh0, vh1, vh2, vh3, vl0, vl1, vl2, vl3;
                LDSM4T(vh0, vh1, vh2, vh3, va);
                LDSM4T(vl0, vl1, vl2, vl3, va + 2u * 64 * SROW);
                MMA16816(o[dt2*2],   ph[0], ph[1], ph[2], ph[3], vh0, vh1);
                MMA16816(o[dt2*2],   pl[0], pl[1], pl[2], pl[3], vh0, vh1);
                MMA16816(o[dt2*2],   ph[0], ph[1], ph[2], ph[3], vl0, vl1);
                MMA16816(o[dt2*2+1], ph[0], ph[1], ph[2], ph[3], vh2, vh3);
                MMA16816(o[dt2*2+1], pl[0], pl[1], pl[2], pl[3], vh2, vh3);
                MMA16816(o[dt2*2+1], ph[0], ph[1], ph[2], ph[3], vl2, vl3);
            }
        }
        __syncthreads();
    }

    const float inv0 = 1.f / lrow[0], inv1 = 1.f / lrow[1];
    const int r0 = qrow0 + w * 16 + g, r1 = r0 + 8;
#pragma unroll
    for (int dt = 0; dt < 8; ++dt) {
        const int col = h * DD + dt * 8 + tg * 2;
        uint32_t hi, lo;
        split2(o[dt][0] * inv0, o[dt][1] * inv0, hi, lo);
        *(uint32_t*)(g_yhi + (size_t)(b * TT + r0) * CC + col) = hi;
        *(uint32_t*)(g_ylo + (size_t)(b * TT + r0) * CC + col) = lo;
        split2(o[dt][2] * inv1, o[dt][3] * inv1, hi, lo);
        *(uint32_t*)(g_yhi + (size_t)(b * TT + r1) * CC + col) = hi;
        *(uint32_t*)(g_ylo + (size_t)(b * TT + r1) * CC + col) = lo;
    }
}

// ---------------------------------------------------------------------------
extern "C" void kernel_launch(void* const* d_in, const int* in_sizes, int n_in,
                              void* d_out, int out_size)
{
    const float* x      = (const float*)d_in[0];
    const float* w_attn = (const float*)d_in[1];
    const float* b_attn = (const float*)d_in[2];
    const float* w_proj = (const float*)d_in[3];
    const float* b_proj = (const float*)d_in[4];
    float* out = (float*)d_out;

    const int gemm_smem = 3 * GSTG;                           // 92160 B
    cudaFuncSetAttribute(gemm_mma_bf16x3<0>, cudaFuncAttributeMaxDynamicSharedMemorySize, gemm_smem);
    cudaFuncSetAttribute(gemm_mma_bf16x3<1>, cudaFuncAttributeMaxDynamicSharedMemorySize, gemm_smem);

    __nv_bfloat16 *xhi, *xlo, *wahi, *walo, *wphi, *wplo, *yhi, *ylo;
    cudaGetSymbolAddress((void**)&xhi,  g_xhi);
    cudaGetSymbolAddress((void**)&xlo,  g_xlo);
    cudaGetSymbolAddress((void**)&wahi, g_wahi);
    cudaGetSymbolAddress((void**)&walo, g_walo);
    cudaGetSymbolAddress((void**)&wphi, g_wphi);
    cudaGetSymbolAddress((void**)&wplo, g_wplo);
    cudaGetSymbolAddress((void**)&yhi,  g_yhi);
    cudaGetSymbolAddress((void**)&ylo,  g_ylo);

    split_x_kernel<<<(MM * CC / 4 + 255) / 256, 256>>>(x);
    transpose_split_kernel<<<dim3(NQKV / 32, CC / 32), dim3(32, 8)>>>(w_attn, wahi, walo, NQKV);
    transpose_split_kernel<<<dim3(CC / 32, CC / 32),   dim3(32, 8)>>>(w_proj, wphi, wplo, CC);

    gemm_mma_bf16x3<0><<<dim3(NQKV / 64, MM / 128), 256, gemm_smem>>>(xhi, xlo, wahi, walo, b_attn, nullptr);
    attn_mma_kernel<<<dim3(TT / 128, HH, BB), 256>>>();
    gemm_mma_bf16x3<1><<<dim3(CC / 64, MM / 128), 256, gemm_smem>>>(yhi, ylo, wphi, wplo, b_proj, out);
}